// round 3
// baseline (speedup 1.0000x reference)
#include <cuda_runtime.h>
#include <cuda_fp16.h>
#include <cstdint>

#define LSEQ 2048
#define NH   8
#define DDIM 64
#define NB   4
#define NBH  32          // NB*NH
#define MDIST 128
#define DBINS 257
#define LDP  72          // padded shared row stride (halves): 144B -> conflict-free ldmatrix
#define LOG2E 1.4426950408889634f

// ---------------- scratch (device globals; no runtime alloc) ----------------
__device__ __half g_qkin[8192 * 256];       // x+pe, fp16
__device__ __half g_Wt[1024 * 256];         // [Wq|Wk]^T, n-major rows, k contiguous
__device__ __half g_Q[NBH * LSEQ * DDIM];   // scaled by d^-0.5 * log2(e), +bias
__device__ __half g_K[NBH * LSEQ * DDIM];
__device__ float  g_V[NBH * LSEQ];          // Vflip[b,h,k] = sigmoid(x[b,L-1-k] . Wv[:,h])
__device__ float  g_S[NBH * DBINS];         // diagonal-bin accumulator

// ---------------- helpers ----------------
__device__ __forceinline__ uint32_t sptr(const void* p) {
    return (uint32_t)__cvta_generic_to_shared(p);
}

__device__ __forceinline__ float ex2f(float x) {
    float r;
    asm("ex2.approx.f32 %0, %1;\n" : "=f"(r) : "f"(x));
    return r;
}

__device__ __forceinline__ void ldsm4(uint32_t& r0, uint32_t& r1, uint32_t& r2, uint32_t& r3,
                                      uint32_t addr) {
    asm volatile("ldmatrix.sync.aligned.m8n8.x4.shared.b16 {%0,%1,%2,%3}, [%4];\n"
                 : "=r"(r0), "=r"(r1), "=r"(r2), "=r"(r3) : "r"(addr));
}

__device__ __forceinline__ void mma16816(float* c, uint32_t a0, uint32_t a1, uint32_t a2,
                                         uint32_t a3, uint32_t b0, uint32_t b1) {
    asm volatile(
        "mma.sync.aligned.m16n8k16.row.col.f32.f16.f16.f32 "
        "{%0,%1,%2,%3},{%4,%5,%6,%7},{%8,%9},{%0,%1,%2,%3};\n"
        : "+f"(c[0]), "+f"(c[1]), "+f"(c[2]), "+f"(c[3])
        : "r"(a0), "r"(a1), "r"(a2), "r"(a3), "r"(b0), "r"(b1));
}

__device__ __forceinline__ void cp_async16(uint32_t dst, const void* src) {
    asm volatile("cp.async.ca.shared.global [%0], [%1], 16;\n" :: "r"(dst), "l"(src));
}
__device__ __forceinline__ void cp_commit() { asm volatile("cp.async.commit_group;\n"); }
__device__ __forceinline__ void cp_wait1()  { asm volatile("cp.async.wait_group 1;\n"); }

// async copy of a 64x64 half tile (global row stride = 64) into padded shared tile
__device__ __forceinline__ void cp_tile(__half* dst, const __half* src, int tid) {
    int r = tid >> 3, c = (tid & 7) << 3;
    cp_async16(sptr(dst + r * LDP + c), src + r * 64 + c);
    cp_async16(sptr(dst + (r + 32) * LDP + c), src + (r + 32) * 64 + c);
}

// 64(M) x 8(N) x 64(K) MMA: A fragments preloaded in regs, B = warp's 8 columns.
// Af[kc][mt][4]: kc = k16 chunk, mt = m16 tile. acc[mt*4 + c].
__device__ __forceinline__ void mma_col8(const __half* Ks, const uint32_t Af[4][4][4],
                                         float acc[16], uint32_t b_addr) {
#pragma unroll
    for (int kh = 0; kh < 2; kh++) {
        uint32_t b0, b1, b2, b3;
        ldsm4(b0, b1, b2, b3, b_addr + kh * 64);   // (n8 x k32): kc=2*kh (b0,b1), kc=2*kh+1 (b2,b3)
#pragma unroll
        for (int mt = 0; mt < 4; mt++) {
            mma16816(acc + mt * 4, Af[2 * kh][mt][0], Af[2 * kh][mt][1],
                     Af[2 * kh][mt][2], Af[2 * kh][mt][3], b0, b1);
            mma16816(acc + mt * 4, Af[2 * kh + 1][mt][0], Af[2 * kh + 1][mt][1],
                     Af[2 * kh + 1][mt][2], Af[2 * kh + 1][mt][3], b2, b3);
        }
    }
}

// sync-copy 64x64 halves (global stride STRIDE) into padded shared tile (for proj kernel)
#define LOAD_TILE(DST, SRC, STRIDE)                                                   \
    {                                                                                 \
        int r_ = tid >> 3, c_ = (tid & 7) << 3;                                       \
        *(int4*)((DST) + r_ * LDP + c_) = *(const int4*)((SRC) + r_ * (STRIDE) + c_); \
        *(int4*)((DST) + (r_ + 32) * LDP + c_) =                                      \
            *(const int4*)((SRC) + (r_ + 32) * (STRIDE) + c_);                        \
    }

// full 64x64 mma loading both A and B from shared (proj kernel, 4x2 warp grid)
__device__ __forceinline__ void mma_tile_64(const __half* Qs, const __half* Ks,
                                            float acc[16], int lane, int wy, int wx) {
    uint32_t a_addr = sptr(Qs + (wy * 16 + (lane & 15)) * LDP + ((lane >> 4) << 3));
    int brow = wx * 32 + (lane & 7) + ((lane >> 4) << 3);
    int bcol = ((lane >> 3) & 1) << 3;
    uint32_t b_addr0 = sptr(Ks + brow * LDP + bcol);
    uint32_t b_addr1 = b_addr0 + 16 * LDP * 2;
#pragma unroll
    for (int kc = 0; kc < 4; kc++) {
        uint32_t a0, a1, a2, a3, b0, b1, b2, b3, b4, b5, b6, b7;
        ldsm4(a0, a1, a2, a3, a_addr + kc * 32);
        ldsm4(b0, b1, b2, b3, b_addr0 + kc * 32);
        ldsm4(b4, b5, b6, b7, b_addr1 + kc * 32);
        mma16816(acc + 0,  a0, a1, a2, a3, b0, b1);
        mma16816(acc + 4,  a0, a1, a2, a3, b2, b3);
        mma16816(acc + 8,  a0, a1, a2, a3, b4, b5);
        mma16816(acc + 12, a0, a1, a2, a3, b6, b7);
    }
}

// ---------------- kernel 1: prep ----------------
__global__ void prep_kernel(const float* __restrict__ x, const float* __restrict__ pe,
                            const float* __restrict__ Wq, const float* __restrict__ Wk) {
    int idx = blockIdx.x * 256 + threadIdx.x;
    if (idx < 8192 * 256) {
        int row = idx >> 8;
        int l = row & (LSEQ - 1);
        int c = idx & 255;
        g_qkin[idx] = __float2half(x[idx] + pe[l * 256 + c]);
        return;
    }
    int i2 = idx - 8192 * 256;
    if (i2 < 1024 * 256) {
        int n = i2 >> 8, kk = i2 & 255;
        float w = (n < 512) ? Wq[kk * 512 + n] : Wk[kk * 512 + (n - 512)];
        g_Wt[i2] = __float2half(w);
        return;
    }
    int i3 = i2 - 1024 * 256;
    if (i3 < NBH * DBINS) g_S[i3] = 0.f;
}

// ---------------- kernel 2: Q/K projection GEMM ----------------
__global__ void __launch_bounds__(256) proj_kernel(const float* __restrict__ bq,
                                                   const float* __restrict__ bk) {
    __shared__ __half As[64 * LDP];
    __shared__ __half Bs[64 * LDP];
    int tid = threadIdx.x, lane = tid & 31, w = tid >> 5, wy = w >> 1, wx = w & 1;
    int m0 = blockIdx.x << 6, n0 = blockIdx.y << 6;
    float acc[16];
#pragma unroll
    for (int i = 0; i < 16; i++) acc[i] = 0.f;
    for (int ks = 0; ks < 4; ks++) {
        __syncthreads();
        LOAD_TILE(As, g_qkin + m0 * 256 + (ks << 6), 256);
        LOAD_TILE(Bs, g_Wt + n0 * 256 + (ks << 6), 256);
        __syncthreads();
        mma_tile_64(As, Bs, acc, lane, wy, wx);
    }
    int g = lane >> 2, tc = lane & 3;
#pragma unroll
    for (int nt = 0; nt < 4; nt++) {
#pragma unroll
        for (int hh = 0; hh < 2; hh++) {
            int row = m0 + wy * 16 + g + (hh << 3);
            int col = n0 + wx * 32 + nt * 8 + tc * 2;
            float v0 = acc[nt * 4 + hh * 2 + 0];
            float v1 = acc[nt * 4 + hh * 2 + 1];
            int b = row >> 11, l = row & (LSEQ - 1);
            if (col < 512) {
                // fold d^-0.5 and log2(e) into Q so score-exp is a single ex2
                v0 = (v0 + bq[col]) * (0.125f * LOG2E);
                v1 = (v1 + bq[col + 1]) * (0.125f * LOG2E);
                int hd = col >> 6, dd = col & 63;
                *(__half2*)(g_Q + ((b * NH + hd) * LSEQ + l) * DDIM + dd) =
                    __floats2half2_rn(v0, v1);
            } else {
                int cj = col - 512;
                v0 += bk[cj];
                v1 += bk[cj + 1];
                int hd = cj >> 6, dd = cj & 63;
                *(__half2*)(g_K + ((b * NH + hd) * LSEQ + l) * DDIM + dd) =
                    __floats2half2_rn(v0, v1);
            }
        }
    }
}

// ---------------- kernel 3: V (sigmoid(x @ Wv), flipped) ----------------
__global__ void __launch_bounds__(256) v_kernel(const float* __restrict__ x,
                                                const float* __restrict__ Wv) {
    __shared__ float Wsh[256 * 8];
    __shared__ float Xsh[32 * 257];
    int tid = threadIdx.x;
    for (int i = tid; i < 2048; i += 256) Wsh[i] = Wv[i];
    int row0 = blockIdx.x * 32;
    for (int i = tid; i < 8192; i += 256) {
        int r = i >> 8, c = i & 255;
        Xsh[r * 257 + c] = x[(row0 + r) * 256 + c];
    }
    __syncthreads();
    int r = tid >> 3, h = tid & 7;
    int bl = row0 + r;
    float s = 0.f;
#pragma unroll 8
    for (int kk = 0; kk < 256; kk++) s += Xsh[r * 257 + kk] * Wsh[kk * 8 + h];
    float v = 1.f / (1.f + __expf(-s));
    int b = bl >> 11, l = bl & (LSEQ - 1);
    g_V[(b * NH + h) * LSEQ + (LSEQ - 1 - l)] = v;
}

// ---------------- kernel 4: attention (pipelined, 1x8 warp grid) ----------------
__global__ void __launch_bounds__(256, 2) attn_kernel() {
    __shared__ __half Qs[64 * LDP];
    __shared__ __half Kb[3][64 * LDP];
    __shared__ float dsh[64];
    __shared__ float Ssh[DBINS];
    __shared__ float Vsh[5 * 64];

    int tid = threadIdx.x, lane = tid & 31, w = tid >> 5;
    int n0w = w << 3;                      // warp's 8 N-columns
    int qt = blockIdx.x, bh = blockIdx.y;
    int q0 = qt << 6;
    const __half* Qg = g_Q + (bh * LSEQ + q0) * DDIM;
    const __half* Kg = g_K + bh * LSEQ * DDIM;

    // async-load Q tile + first two K tiles
    cp_tile(Qs, Qg, tid);
    cp_tile(Kb[0], Kg, tid);
    cp_commit();                    // group 0: Qs + K0
    cp_tile(Kb[1], Kg + 64 * DDIM, tid);
    cp_commit();                    // group 1: K1

    if (tid < 64) dsh[tid] = 0.f;
    if (tid < DBINS) Ssh[tid] = 0.f;
    if (tid == 255) Ssh[256] = 0.f;

    cp_wait1();                     // Qs + K0 landed
    __syncthreads();

    // hoist all A (Q) fragments: full 64 M-rows, 64 K. Af[kc][mt][4]
    uint32_t Af[4][4][4];
#pragma unroll
    for (int mt = 0; mt < 4; mt++) {
        uint32_t a_addr = sptr(Qs + (mt * 16 + (lane & 15)) * LDP + ((lane >> 4) << 3));
#pragma unroll
        for (int kc = 0; kc < 4; kc++)
            ldsm4(Af[kc][mt][0], Af[kc][mt][1], Af[kc][mt][2], Af[kc][mt][3],
                  a_addr + kc * 32);
    }

    int g = lane >> 2, tc = lane & 3;
    uint32_t b_lane_off = (uint32_t)(((n0w + (lane & 7)) * LDP + ((lane >> 3) << 3)) * 2);
    float dsum[8];
#pragma unroll
    for (int i = 0; i < 8; i++) dsum[i] = 0.f;

    // ---- Phase 1: softmax denominators over all 32 K tiles ----
    for (int kt = 0; kt < 32; kt++) {
        if (kt > 0) { cp_wait1(); __syncthreads(); }
        if (kt + 2 < 32) cp_tile(Kb[(kt + 2) % 3], Kg + (kt + 2) * 64 * DDIM, tid);
        cp_commit();                // one group per iteration -> constant wait_group 1
        float acc[16];
#pragma unroll
        for (int i = 0; i < 16; i++) acc[i] = 0.f;
        mma_col8(Kb[kt % 3], Af, acc, sptr(Kb[kt % 3]) + b_lane_off);
#pragma unroll
        for (int mt = 0; mt < 4; mt++) {
            dsum[2 * mt + 0] += ex2f(acc[mt * 4 + 0]) + ex2f(acc[mt * 4 + 1]);
            dsum[2 * mt + 1] += ex2f(acc[mt * 4 + 2]) + ex2f(acc[mt * 4 + 3]);
        }
    }
    // reduce over the 4 tc-lanes sharing a row, then shared atomics across warps
#pragma unroll
    for (int i = 0; i < 8; i++) {
        dsum[i] += __shfl_xor_sync(0xffffffffu, dsum[i], 1);
        dsum[i] += __shfl_xor_sync(0xffffffffu, dsum[i], 2);
    }
    if (tc == 0) {
#pragma unroll
        for (int mt = 0; mt < 4; mt++) {
            atomicAdd(&dsh[mt * 16 + g], dsum[2 * mt + 0]);
            atomicAdd(&dsh[mt * 16 + g + 8], dsum[2 * mt + 1]);
        }
    }
    __syncthreads();

    int kt_lo = qt >= 2 ? qt - 2 : 0;
    int kt_hi = qt <= 29 ? qt + 2 : 31;
    int nb = kt_hi - kt_lo + 1;

    if (tid < 64) dsh[tid] = 1.f / dsh[tid];
    const float* Vg = g_V + bh * LSEQ;
    for (int i = tid; i < nb * 64; i += 256) Vsh[i] = Vg[kt_lo * 64 + i];
    __syncthreads();   // buffers free + dsh inverted

    // hoist inverse denominators for this thread's 8 rows
    float inv[8];
#pragma unroll
    for (int mt = 0; mt < 4; mt++) {
        inv[2 * mt + 0] = dsh[mt * 16 + g];
        inv[2 * mt + 1] = dsh[mt * 16 + g + 8];
    }

    // ---- Phase 2: band tiles, bin by diagonal j = 128 + k - q ----
    cp_tile(Kb[0], Kg + kt_lo * 64 * DDIM, tid);
    cp_commit();
    if (nb > 1) cp_tile(Kb[1], Kg + (kt_lo + 1) * 64 * DDIM, tid);
    cp_commit();

    for (int i = 0; i < nb; i++) {
        int kt = kt_lo + i;
        cp_wait1();
        __syncthreads();
        if (i + 2 < nb) cp_tile(Kb[(i + 2) % 3], Kg + (kt + 2) * 64 * DDIM, tid);
        cp_commit();
        float acc[16];
#pragma unroll
        for (int ii = 0; ii < 16; ii++) acc[ii] = 0.f;
        mma_col8(Kb[i % 3], Af, acc, sptr(Kb[i % 3]) + b_lane_off);
        int kbase = (kt << 6) + n0w + tc * 2;
#pragma unroll
        for (int mt = 0; mt < 4; mt++) {
#pragma unroll
            for (int hh = 0; hh < 2; hh++) {
                int row = mt * 16 + g + (hh << 3);
                int q = q0 + row;
                float iv = inv[2 * mt + hh];
#pragma unroll
                for (int cc = 0; cc < 2; cc++) {
                    int k = kbase + cc;
                    int j = MDIST + k - q;
                    if (j >= 0 && j < DBINS) {
                        float e = ex2f(acc[mt * 4 + hh * 2 + cc]);
                        atomicAdd(&Ssh[j], e * iv * Vsh[k - (kt_lo << 6)]);
                    }
                }
            }
        }
    }
    __syncthreads();
    if (tid < DBINS) atomicAdd(&g_S[bh * DBINS + tid], Ssh[tid]);
    if (tid == 255) atomicAdd(&g_S[bh * DBINS + 256], Ssh[256]);
}

// ---------------- kernel 5: window smoothing + output ----------------
__global__ void final_kernel(float* __restrict__ out) {
    int idx = blockIdx.x * 256 + threadIdx.x;
    if (idx >= NB * DBINS * NH) return;
    int h = idx & 7;
    int j = (idx >> 3) % DBINS;
    int b = idx / (DBINS * NH);
    const float* S = g_S + (b * NH + h) * DBINS;
    float s = S[j];
    float cnt = 1.f;
    if (j > 0)         { s += S[j - 1]; cnt += 1.f; }
    if (j < DBINS - 1) { s += S[j + 1]; cnt += 1.f; }
    out[idx] = s / cnt;
}

// ---------------- launch ----------------
extern "C" void kernel_launch(void* const* d_in, const int* in_sizes, int n_in,
                              void* d_out, int out_size) {
    const float* x  = (const float*)d_in[0];
    const float* pe = (const float*)d_in[1];
    const float* Wq = (const float*)d_in[2];
    const float* bq = (const float*)d_in[3];
    const float* Wk = (const float*)d_in[4];
    const float* bk = (const float*)d_in[5];
    const float* Wv = (const float*)d_in[6];
    float* out = (float*)d_out;

    int prep_total = 8192 * 256 + 1024 * 256 + NBH * DBINS;
    prep_kernel<<<(prep_total + 255) / 256, 256>>>(x, pe, Wq, Wk);
    proj_kernel<<<dim3(128, 16), 256>>>(bq, bk);
    v_kernel<<<256, 256>>>(x, Wv);
    attn_kernel<<<dim3(32, 32), 256>>>();
    final_kernel<<<(NB * DBINS * NH + 255) / 256, 256>>>(out);
}

// round 4
// speedup vs baseline: 1.0905x; 1.0905x over previous
#include <cuda_runtime.h>
#include <cuda_fp16.h>
#include <cstdint>

#define LSEQ 2048
#define NH   8
#define DDIM 64
#define NB   4
#define NBH  32          // NB*NH
#define MDIST 128
#define DBINS 257
#define LDP  72          // padded shared row stride (halves): 144B -> conflict-free ldmatrix
#define LOG2E 1.4426950408889634f

// ---------------- scratch (device globals; no runtime alloc) ----------------
__device__ __half g_qkin[8192 * 256];       // x+pe, fp16
__device__ __half g_Wt[1024 * 256];         // [Wq|Wk]^T, n-major rows, k contiguous
__device__ __half g_Q[NBH * LSEQ * DDIM];   // scaled by d^-0.5 * log2(e), +bias
__device__ __half g_K[NBH * LSEQ * DDIM];
__device__ float  g_V[NBH * LSEQ];          // Vflip[b,h,k] = sigmoid(x[b,L-1-k] . Wv[:,h])
__device__ float  g_S[NBH * DBINS];         // diagonal-bin accumulator

// ---------------- helpers ----------------
__device__ __forceinline__ uint32_t sptr(const void* p) {
    return (uint32_t)__cvta_generic_to_shared(p);
}

__device__ __forceinline__ float ex2f(float x) {
    float r;
    asm("ex2.approx.f32 %0, %1;\n" : "=f"(r) : "f"(x));
    return r;
}

__device__ __forceinline__ void ldsm4(uint32_t& r0, uint32_t& r1, uint32_t& r2, uint32_t& r3,
                                      uint32_t addr) {
    asm volatile("ldmatrix.sync.aligned.m8n8.x4.shared.b16 {%0,%1,%2,%3}, [%4];\n"
                 : "=r"(r0), "=r"(r1), "=r"(r2), "=r"(r3) : "r"(addr));
}

__device__ __forceinline__ void mma16816(float* c, uint32_t a0, uint32_t a1, uint32_t a2,
                                         uint32_t a3, uint32_t b0, uint32_t b1) {
    asm volatile(
        "mma.sync.aligned.m16n8k16.row.col.f32.f16.f16.f32 "
        "{%0,%1,%2,%3},{%4,%5,%6,%7},{%8,%9},{%0,%1,%2,%3};\n"
        : "+f"(c[0]), "+f"(c[1]), "+f"(c[2]), "+f"(c[3])
        : "r"(a0), "r"(a1), "r"(a2), "r"(a3), "r"(b0), "r"(b1));
}

__device__ __forceinline__ void cp_async16(uint32_t dst, const void* src) {
    asm volatile("cp.async.ca.shared.global [%0], [%1], 16;\n" :: "r"(dst), "l"(src));
}
__device__ __forceinline__ void cp_commit() { asm volatile("cp.async.commit_group;\n"); }
__device__ __forceinline__ void cp_wait1()  { asm volatile("cp.async.wait_group 1;\n"); }

// async copy of a 64x64 half tile (global row stride = 64) into padded shared tile
__device__ __forceinline__ void cp_tile(__half* dst, const __half* src, int tid) {
    int r = tid >> 3, c = (tid & 7) << 3;
    cp_async16(sptr(dst + r * LDP + c), src + r * 64 + c);
    cp_async16(sptr(dst + (r + 32) * LDP + c), src + (r + 32) * 64 + c);
}

// 32(M) x 16(N) x 64(K) per-warp MMA: A fragments preloaded, B read from shared.
// Af[kc][mt][4], acc[mt][nt][4]. Warp covers rows wm*32..+31, cols wn*16..+15.
__device__ __forceinline__ void mma_2x2(const __half* Ks, const uint32_t Af[4][2][4],
                                        float acc[2][2][4], int lane, int wn) {
#pragma unroll
    for (int kh = 0; kh < 2; kh++) {
#pragma unroll
        for (int nt = 0; nt < 2; nt++) {
            uint32_t addr = sptr(Ks + (wn * 16 + nt * 8 + (lane & 7)) * LDP +
                                 kh * 32 + ((lane >> 3) << 3));
            uint32_t b0, b1, b2, b3;
            ldsm4(b0, b1, b2, b3, addr);
#pragma unroll
            for (int mt = 0; mt < 2; mt++) {
                mma16816(acc[mt][nt], Af[2 * kh][mt][0], Af[2 * kh][mt][1],
                         Af[2 * kh][mt][2], Af[2 * kh][mt][3], b0, b1);
                mma16816(acc[mt][nt], Af[2 * kh + 1][mt][0], Af[2 * kh + 1][mt][1],
                         Af[2 * kh + 1][mt][2], Af[2 * kh + 1][mt][3], b2, b3);
            }
        }
    }
}

// sync-copy 64x64 halves (global stride STRIDE) into padded shared tile (for proj kernel)
#define LOAD_TILE(DST, SRC, STRIDE)                                                   \
    {                                                                                 \
        int r_ = tid >> 3, c_ = (tid & 7) << 3;                                       \
        *(int4*)((DST) + r_ * LDP + c_) = *(const int4*)((SRC) + r_ * (STRIDE) + c_); \
        *(int4*)((DST) + (r_ + 32) * LDP + c_) =                                      \
            *(const int4*)((SRC) + (r_ + 32) * (STRIDE) + c_);                        \
    }

// full 64x64 mma loading both A and B from shared (proj kernel, 4x2 warp grid)
__device__ __forceinline__ void mma_tile_64(const __half* Qs, const __half* Ks,
                                            float acc[16], int lane, int wy, int wx) {
    uint32_t a_addr = sptr(Qs + (wy * 16 + (lane & 15)) * LDP + ((lane >> 4) << 3));
    int brow = wx * 32 + (lane & 7) + ((lane >> 4) << 3);
    int bcol = ((lane >> 3) & 1) << 3;
    uint32_t b_addr0 = sptr(Ks + brow * LDP + bcol);
    uint32_t b_addr1 = b_addr0 + 16 * LDP * 2;
#pragma unroll
    for (int kc = 0; kc < 4; kc++) {
        uint32_t a0, a1, a2, a3, b0, b1, b2, b3, b4, b5, b6, b7;
        ldsm4(a0, a1, a2, a3, a_addr + kc * 32);
        ldsm4(b0, b1, b2, b3, b_addr0 + kc * 32);
        ldsm4(b4, b5, b6, b7, b_addr1 + kc * 32);
        mma16816(acc + 0,  a0, a1, a2, a3, b0, b1);
        mma16816(acc + 4,  a0, a1, a2, a3, b2, b3);
        mma16816(acc + 8,  a0, a1, a2, a3, b4, b5);
        mma16816(acc + 12, a0, a1, a2, a3, b6, b7);
    }
}

// ---------------- kernel 1: prep ----------------
__global__ void prep_kernel(const float* __restrict__ x, const float* __restrict__ pe,
                            const float* __restrict__ Wq, const float* __restrict__ Wk) {
    int idx = blockIdx.x * 256 + threadIdx.x;
    if (idx < 8192 * 256) {
        int row = idx >> 8;
        int l = row & (LSEQ - 1);
        int c = idx & 255;
        g_qkin[idx] = __float2half(x[idx] + pe[l * 256 + c]);
        return;
    }
    int i2 = idx - 8192 * 256;
    if (i2 < 1024 * 256) {
        int n = i2 >> 8, kk = i2 & 255;
        float w = (n < 512) ? Wq[kk * 512 + n] : Wk[kk * 512 + (n - 512)];
        g_Wt[i2] = __float2half(w);
        return;
    }
    int i3 = i2 - 1024 * 256;
    if (i3 < NBH * DBINS) g_S[i3] = 0.f;
}

// ---------------- kernel 2: Q/K projection GEMM ----------------
__global__ void __launch_bounds__(256) proj_kernel(const float* __restrict__ bq,
                                                   const float* __restrict__ bk) {
    __shared__ __half As[64 * LDP];
    __shared__ __half Bs[64 * LDP];
    int tid = threadIdx.x, lane = tid & 31, w = tid >> 5, wy = w >> 1, wx = w & 1;
    int m0 = blockIdx.x << 6, n0 = blockIdx.y << 6;
    float acc[16];
#pragma unroll
    for (int i = 0; i < 16; i++) acc[i] = 0.f;
    for (int ks = 0; ks < 4; ks++) {
        __syncthreads();
        LOAD_TILE(As, g_qkin + m0 * 256 + (ks << 6), 256);
        LOAD_TILE(Bs, g_Wt + n0 * 256 + (ks << 6), 256);
        __syncthreads();
        mma_tile_64(As, Bs, acc, lane, wy, wx);
    }
    int g = lane >> 2, tc = lane & 3;
#pragma unroll
    for (int nt = 0; nt < 4; nt++) {
#pragma unroll
        for (int hh = 0; hh < 2; hh++) {
            int row = m0 + wy * 16 + g + (hh << 3);
            int col = n0 + wx * 32 + nt * 8 + tc * 2;
            float v0 = acc[nt * 4 + hh * 2 + 0];
            float v1 = acc[nt * 4 + hh * 2 + 1];
            int b = row >> 11, l = row & (LSEQ - 1);
            if (col < 512) {
                // fold d^-0.5 and log2(e) into Q so score-exp is a single ex2
                v0 = (v0 + bq[col]) * (0.125f * LOG2E);
                v1 = (v1 + bq[col + 1]) * (0.125f * LOG2E);
                int hd = col >> 6, dd = col & 63;
                *(__half2*)(g_Q + ((b * NH + hd) * LSEQ + l) * DDIM + dd) =
                    __floats2half2_rn(v0, v1);
            } else {
                int cj = col - 512;
                v0 += bk[cj];
                v1 += bk[cj + 1];
                int hd = cj >> 6, dd = cj & 63;
                *(__half2*)(g_K + ((b * NH + hd) * LSEQ + l) * DDIM + dd) =
                    __floats2half2_rn(v0, v1);
            }
        }
    }
}

// ---------------- kernel 3: V (sigmoid(x @ Wv), flipped) ----------------
__global__ void __launch_bounds__(256) v_kernel(const float* __restrict__ x,
                                                const float* __restrict__ Wv) {
    __shared__ float Wsh[256 * 8];
    __shared__ float Xsh[32 * 257];
    int tid = threadIdx.x;
    for (int i = tid; i < 2048; i += 256) Wsh[i] = Wv[i];
    int row0 = blockIdx.x * 32;
    for (int i = tid; i < 8192; i += 256) {
        int r = i >> 8, c = i & 255;
        Xsh[r * 257 + c] = x[(row0 + r) * 256 + c];
    }
    __syncthreads();
    int r = tid >> 3, h = tid & 7;
    int bl = row0 + r;
    float s = 0.f;
#pragma unroll 8
    for (int kk = 0; kk < 256; kk++) s += Xsh[r * 257 + kk] * Wsh[kk * 8 + h];
    float v = 1.f / (1.f + __expf(-s));
    int b = bl >> 11, l = bl & (LSEQ - 1);
    g_V[(b * NH + h) * LSEQ + (LSEQ - 1 - l)] = v;
}

// ---------------- kernel 4: attention (pipelined, 2x4 warp grid, A hoisted) ----------------
__global__ void __launch_bounds__(256, 3) attn_kernel() {
    __shared__ __half Qs[64 * LDP];
    __shared__ __half Kb[3][64 * LDP];
    __shared__ float dsh[64];
    __shared__ float Ssh[DBINS];
    __shared__ float Vsh[5 * 64];

    int tid = threadIdx.x, lane = tid & 31, w = tid >> 5;
    int wm = w >> 2, wn = w & 3;           // 2 M-splits x 4 N-splits
    int qt = blockIdx.x, bh = blockIdx.y;
    int q0 = qt << 6;
    const __half* Qg = g_Q + (bh * LSEQ + q0) * DDIM;
    const __half* Kg = g_K + bh * LSEQ * DDIM;

    // async-load Q tile + first two K tiles
    cp_tile(Qs, Qg, tid);
    cp_tile(Kb[0], Kg, tid);
    cp_commit();                    // group 0: Qs + K0
    cp_tile(Kb[1], Kg + 64 * DDIM, tid);
    cp_commit();                    // group 1: K1

    if (tid < 64) dsh[tid] = 0.f;
    if (tid < DBINS) Ssh[tid] = 0.f;
    if (tid == 255) Ssh[256] = 0.f;

    cp_wait1();                     // Qs + K0 landed
    __syncthreads();

    // hoist A (Q) fragments for this warp's 32 rows: Af[kc][mt][4] = 32 regs
    uint32_t Af[4][2][4];
#pragma unroll
    for (int mt = 0; mt < 2; mt++) {
        uint32_t a_addr =
            sptr(Qs + (wm * 32 + mt * 16 + (lane & 15)) * LDP + ((lane >> 4) << 3));
#pragma unroll
        for (int kc = 0; kc < 4; kc++)
            ldsm4(Af[kc][mt][0], Af[kc][mt][1], Af[kc][mt][2], Af[kc][mt][3],
                  a_addr + kc * 32);
    }

    int g = lane >> 2, tc = lane & 3;
    float dsum[4];                          // (mt, hh)
#pragma unroll
    for (int i = 0; i < 4; i++) dsum[i] = 0.f;

    // ---- Phase 1: softmax denominators over all 32 K tiles ----
    for (int kt = 0; kt < 32; kt++) {
        if (kt > 0) { cp_wait1(); __syncthreads(); }
        if (kt + 2 < 32) cp_tile(Kb[(kt + 2) % 3], Kg + (kt + 2) * 64 * DDIM, tid);
        cp_commit();                // one group per iteration -> constant wait_group 1
        float acc[2][2][4];
#pragma unroll
        for (int a = 0; a < 2; a++)
#pragma unroll
            for (int bb = 0; bb < 2; bb++)
#pragma unroll
                for (int cix = 0; cix < 4; cix++) acc[a][bb][cix] = 0.f;
        mma_2x2(Kb[kt % 3], Af, acc, lane, wn);
#pragma unroll
        for (int mt = 0; mt < 2; mt++)
#pragma unroll
            for (int nt = 0; nt < 2; nt++) {
                dsum[2 * mt + 0] += ex2f(acc[mt][nt][0]) + ex2f(acc[mt][nt][1]);
                dsum[2 * mt + 1] += ex2f(acc[mt][nt][2]) + ex2f(acc[mt][nt][3]);
            }
    }
    // reduce over the 4 tc-lanes sharing a row, then shared atomics across warps
#pragma unroll
    for (int i = 0; i < 4; i++) {
        dsum[i] += __shfl_xor_sync(0xffffffffu, dsum[i], 1);
        dsum[i] += __shfl_xor_sync(0xffffffffu, dsum[i], 2);
    }
    if (tc == 0) {
#pragma unroll
        for (int mt = 0; mt < 2; mt++) {
            atomicAdd(&dsh[wm * 32 + mt * 16 + g], dsum[2 * mt + 0]);
            atomicAdd(&dsh[wm * 32 + mt * 16 + g + 8], dsum[2 * mt + 1]);
        }
    }
    __syncthreads();

    int kt_lo = qt >= 2 ? qt - 2 : 0;
    int kt_hi = qt <= 29 ? qt + 2 : 31;
    int nb = kt_hi - kt_lo + 1;

    if (tid < 64) dsh[tid] = 1.f / dsh[tid];
    const float* Vg = g_V + bh * LSEQ;
    for (int i = tid; i < nb * 64; i += 256) Vsh[i] = Vg[kt_lo * 64 + i];
    __syncthreads();   // buffers free + dsh inverted

    // hoist inverse denominators for this thread's 4 rows
    float inv[4];
#pragma unroll
    for (int mt = 0; mt < 2; mt++) {
        inv[2 * mt + 0] = dsh[wm * 32 + mt * 16 + g];
        inv[2 * mt + 1] = dsh[wm * 32 + mt * 16 + g + 8];
    }

    // ---- Phase 2: band tiles, bin by diagonal j = 128 + k - q ----
    cp_tile(Kb[0], Kg + kt_lo * 64 * DDIM, tid);
    cp_commit();
    if (nb > 1) cp_tile(Kb[1], Kg + (kt_lo + 1) * 64 * DDIM, tid);
    cp_commit();

    for (int i = 0; i < nb; i++) {
        int kt = kt_lo + i;
        cp_wait1();
        __syncthreads();
        if (i + 2 < nb) cp_tile(Kb[(i + 2) % 3], Kg + (kt + 2) * 64 * DDIM, tid);
        cp_commit();
        float acc[2][2][4];
#pragma unroll
        for (int a = 0; a < 2; a++)
#pragma unroll
            for (int bb = 0; bb < 2; bb++)
#pragma unroll
                for (int cix = 0; cix < 4; cix++) acc[a][bb][cix] = 0.f;
        mma_2x2(Kb[i % 3], Af, acc, lane, wn);
#pragma unroll
        for (int mt = 0; mt < 2; mt++) {
#pragma unroll
            for (int hh = 0; hh < 2; hh++) {
                int q = q0 + wm * 32 + mt * 16 + g + (hh << 3);
                float iv = inv[2 * mt + hh];
#pragma unroll
                for (int nt = 0; nt < 2; nt++) {
                    int kbase = (kt << 6) + wn * 16 + nt * 8 + tc * 2;
#pragma unroll
                    for (int cc = 0; cc < 2; cc++) {
                        int k = kbase + cc;
                        int j = MDIST + k - q;
                        if (j >= 0 && j < DBINS) {
                            float e = ex2f(acc[mt][nt][hh * 2 + cc]);
                            atomicAdd(&Ssh[j], e * iv * Vsh[k - (kt_lo << 6)]);
                        }
                    }
                }
            }
        }
    }
    __syncthreads();
    if (tid < DBINS) atomicAdd(&g_S[bh * DBINS + tid], Ssh[tid]);
    if (tid == 255) atomicAdd(&g_S[bh * DBINS + 256], Ssh[256]);
}

// ---------------- kernel 5: window smoothing + output ----------------
__global__ void final_kernel(float* __restrict__ out) {
    int idx = blockIdx.x * 256 + threadIdx.x;
    if (idx >= NB * DBINS * NH) return;
    int h = idx & 7;
    int j = (idx >> 3) % DBINS;
    int b = idx / (DBINS * NH);
    const float* S = g_S + (b * NH + h) * DBINS;
    float s = S[j];
    float cnt = 1.f;
    if (j > 0)         { s += S[j - 1]; cnt += 1.f; }
    if (j < DBINS - 1) { s += S[j + 1]; cnt += 1.f; }
    out[idx] = s / cnt;
}

// ---------------- launch ----------------
extern "C" void kernel_launch(void* const* d_in, const int* in_sizes, int n_in,
                              void* d_out, int out_size) {
    const float* x  = (const float*)d_in[0];
    const float* pe = (const float*)d_in[1];
    const float* Wq = (const float*)d_in[2];
    const float* bq = (const float*)d_in[3];
    const float* Wk = (const float*)d_in[4];
    const float* bk = (const float*)d_in[5];
    const float* Wv = (const float*)d_in[6];
    float* out = (float*)d_out;

    int prep_total = 8192 * 256 + 1024 * 256 + NBH * DBINS;
    prep_kernel<<<(prep_total + 255) / 256, 256>>>(x, pe, Wq, Wk);
    proj_kernel<<<dim3(128, 16), 256>>>(bq, bk);
    v_kernel<<<256, 256>>>(x, Wv);
    attn_kernel<<<dim3(32, 32), 256>>>();
    final_kernel<<<(NB * DBINS * NH + 255) / 256, 256>>>(out);
}

// round 5
// speedup vs baseline: 1.1116x; 1.0193x over previous
#include <cuda_runtime.h>
#include <cuda_fp16.h>
#include <cstdint>

#define LSEQ 2048
#define NH   8
#define DDIM 64
#define NB   4
#define NBH  32          // NB*NH
#define MDIST 128
#define DBINS 257
#define LDP  72          // padded shared row stride (halves): 144B -> conflict-free ldmatrix
#define LOG2E 1.4426950408889634f

// ---------------- scratch (device globals; no runtime alloc) ----------------
__device__ __half g_qkin[8192 * 256];       // x+pe, fp16
__device__ __half g_Wt[1024 * 256];         // [Wq|Wk]^T, n-major rows, k contiguous
__device__ __half g_Q[NBH * LSEQ * DDIM];   // scaled by d^-0.5 * log2(e), +bias
__device__ __half g_K[NBH * LSEQ * DDIM];
__device__ float  g_V[NBH * LSEQ];          // Vflip[b,h,k] = sigmoid(x[b,L-1-k] . Wv[:,h])
__device__ float  g_S[NBH * DBINS];         // diagonal-bin accumulator

// ---------------- helpers ----------------
__device__ __forceinline__ uint32_t sptr(const void* p) {
    return (uint32_t)__cvta_generic_to_shared(p);
}

__device__ __forceinline__ uint32_t h2ex2(uint32_t x) {   // packed half2 2^x
    uint32_t r;
    asm("ex2.approx.f16x2 %0, %1;\n" : "=r"(r) : "r"(x));
    return r;
}

__device__ __forceinline__ uint32_t h2add(uint32_t a, uint32_t b) {
    uint32_t r;
    asm("add.f16x2 %0, %1, %2;\n" : "=r"(r) : "r"(a), "r"(b));
    return r;
}

__device__ __forceinline__ void ldsm4(uint32_t& r0, uint32_t& r1, uint32_t& r2, uint32_t& r3,
                                      uint32_t addr) {
    asm volatile("ldmatrix.sync.aligned.m8n8.x4.shared.b16 {%0,%1,%2,%3}, [%4];\n"
                 : "=r"(r0), "=r"(r1), "=r"(r2), "=r"(r3) : "r"(addr));
}

// fp32-accumulate variant (proj kernel)
__device__ __forceinline__ void mma16816(float* c, uint32_t a0, uint32_t a1, uint32_t a2,
                                         uint32_t a3, uint32_t b0, uint32_t b1) {
    asm volatile(
        "mma.sync.aligned.m16n8k16.row.col.f32.f16.f16.f32 "
        "{%0,%1,%2,%3},{%4,%5,%6,%7},{%8,%9},{%0,%1,%2,%3};\n"
        : "+f"(c[0]), "+f"(c[1]), "+f"(c[2]), "+f"(c[3])
        : "r"(a0), "r"(a1), "r"(a2), "r"(a3), "r"(b0), "r"(b1));
}

// f16-accumulate variant (attention): C/D = 2 packed-half2 regs
__device__ __forceinline__ void mma16816h(uint32_t& c0, uint32_t& c1, uint32_t a0, uint32_t a1,
                                          uint32_t a2, uint32_t a3, uint32_t b0, uint32_t b1) {
    asm volatile(
        "mma.sync.aligned.m16n8k16.row.col.f16.f16.f16.f16 "
        "{%0,%1},{%2,%3,%4,%5},{%6,%7},{%0,%1};\n"
        : "+r"(c0), "+r"(c1)
        : "r"(a0), "r"(a1), "r"(a2), "r"(a3), "r"(b0), "r"(b1));
}

__device__ __forceinline__ void cp_async16(uint32_t dst, const void* src) {
    asm volatile("cp.async.ca.shared.global [%0], [%1], 16;\n" :: "r"(dst), "l"(src));
}
__device__ __forceinline__ void cp_commit() { asm volatile("cp.async.commit_group;\n"); }
__device__ __forceinline__ void cp_wait1()  { asm volatile("cp.async.wait_group 1;\n"); }

// async copy of a 64x64 half tile (global row stride = 64) into padded shared tile
__device__ __forceinline__ void cp_tile(__half* dst, const __half* src, int tid) {
    int r = tid >> 3, c = (tid & 7) << 3;
    cp_async16(sptr(dst + r * LDP + c), src + r * 64 + c);
    cp_async16(sptr(dst + (r + 32) * LDP + c), src + (r + 32) * 64 + c);
}

// 16(M)x32(N)x64(K) per-warp MMA, f16 accumulate. A fragments preloaded.
// acc[nt][0] = row g, cols nt*8+tc*2(+1); acc[nt][1] = row g+8.
__device__ __forceinline__ void mma_h(const __half* Ks, const uint32_t Af[4][4],
                                      uint32_t acc[4][2], int lane, int wx) {
    int brow = wx * 32 + (lane & 7) + ((lane >> 4) << 3);
    int bcol = ((lane >> 3) & 1) << 3;
    uint32_t b_addr0 = sptr(Ks + brow * LDP + bcol);
    uint32_t b_addr1 = b_addr0 + 16 * LDP * 2;
#pragma unroll
    for (int kc = 0; kc < 4; kc++) {
        uint32_t b0, b1, b2, b3, b4, b5, b6, b7;
        ldsm4(b0, b1, b2, b3, b_addr0 + kc * 32);
        ldsm4(b4, b5, b6, b7, b_addr1 + kc * 32);
        mma16816h(acc[0][0], acc[0][1], Af[kc][0], Af[kc][1], Af[kc][2], Af[kc][3], b0, b1);
        mma16816h(acc[1][0], acc[1][1], Af[kc][0], Af[kc][1], Af[kc][2], Af[kc][3], b2, b3);
        mma16816h(acc[2][0], acc[2][1], Af[kc][0], Af[kc][1], Af[kc][2], Af[kc][3], b4, b5);
        mma16816h(acc[3][0], acc[3][1], Af[kc][0], Af[kc][1], Af[kc][2], Af[kc][3], b6, b7);
    }
}

// sync-copy 64x64 halves (global stride STRIDE) into padded shared tile (for proj kernel)
#define LOAD_TILE(DST, SRC, STRIDE)                                                   \
    {                                                                                 \
        int r_ = tid >> 3, c_ = (tid & 7) << 3;                                       \
        *(int4*)((DST) + r_ * LDP + c_) = *(const int4*)((SRC) + r_ * (STRIDE) + c_); \
        *(int4*)((DST) + (r_ + 32) * LDP + c_) =                                      \
            *(const int4*)((SRC) + (r_ + 32) * (STRIDE) + c_);                        \
    }

// full 64x64 mma loading both A and B from shared (proj kernel, 4x2 warp grid)
__device__ __forceinline__ void mma_tile_64(const __half* Qs, const __half* Ks,
                                            float acc[16], int lane, int wy, int wx) {
    uint32_t a_addr = sptr(Qs + (wy * 16 + (lane & 15)) * LDP + ((lane >> 4) << 3));
    int brow = wx * 32 + (lane & 7) + ((lane >> 4) << 3);
    int bcol = ((lane >> 3) & 1) << 3;
    uint32_t b_addr0 = sptr(Ks + brow * LDP + bcol);
    uint32_t b_addr1 = b_addr0 + 16 * LDP * 2;
#pragma unroll
    for (int kc = 0; kc < 4; kc++) {
        uint32_t a0, a1, a2, a3, b0, b1, b2, b3, b4, b5, b6, b7;
        ldsm4(a0, a1, a2, a3, a_addr + kc * 32);
        ldsm4(b0, b1, b2, b3, b_addr0 + kc * 32);
        ldsm4(b4, b5, b6, b7, b_addr1 + kc * 32);
        mma16816(acc + 0,  a0, a1, a2, a3, b0, b1);
        mma16816(acc + 4,  a0, a1, a2, a3, b2, b3);
        mma16816(acc + 8,  a0, a1, a2, a3, b4, b5);
        mma16816(acc + 12, a0, a1, a2, a3, b6, b7);
    }
}

// ---------------- kernel 1: prep ----------------
__global__ void prep_kernel(const float* __restrict__ x, const float* __restrict__ pe,
                            const float* __restrict__ Wq, const float* __restrict__ Wk) {
    int idx = blockIdx.x * 256 + threadIdx.x;
    if (idx < 8192 * 256) {
        int row = idx >> 8;
        int l = row & (LSEQ - 1);
        int c = idx & 255;
        g_qkin[idx] = __float2half(x[idx] + pe[l * 256 + c]);
        return;
    }
    int i2 = idx - 8192 * 256;
    if (i2 < 1024 * 256) {
        int n = i2 >> 8, kk = i2 & 255;
        float w = (n < 512) ? Wq[kk * 512 + n] : Wk[kk * 512 + (n - 512)];
        g_Wt[i2] = __float2half(w);
        return;
    }
    int i3 = i2 - 1024 * 256;
    if (i3 < NBH * DBINS) g_S[i3] = 0.f;
}

// ---------------- kernel 2: Q/K projection GEMM ----------------
__global__ void __launch_bounds__(256) proj_kernel(const float* __restrict__ bq,
                                                   const float* __restrict__ bk) {
    __shared__ __half As[64 * LDP];
    __shared__ __half Bs[64 * LDP];
    int tid = threadIdx.x, lane = tid & 31, w = tid >> 5, wy = w >> 1, wx = w & 1;
    int m0 = blockIdx.x << 6, n0 = blockIdx.y << 6;
    float acc[16];
#pragma unroll
    for (int i = 0; i < 16; i++) acc[i] = 0.f;
    for (int ks = 0; ks < 4; ks++) {
        __syncthreads();
        LOAD_TILE(As, g_qkin + m0 * 256 + (ks << 6), 256);
        LOAD_TILE(Bs, g_Wt + n0 * 256 + (ks << 6), 256);
        __syncthreads();
        mma_tile_64(As, Bs, acc, lane, wy, wx);
    }
    int g = lane >> 2, tc = lane & 3;
#pragma unroll
    for (int nt = 0; nt < 4; nt++) {
#pragma unroll
        for (int hh = 0; hh < 2; hh++) {
            int row = m0 + wy * 16 + g + (hh << 3);
            int col = n0 + wx * 32 + nt * 8 + tc * 2;
            float v0 = acc[nt * 4 + hh * 2 + 0];
            float v1 = acc[nt * 4 + hh * 2 + 1];
            int b = row >> 11, l = row & (LSEQ - 1);
            if (col < 512) {
                // fold d^-0.5 and log2(e) into Q so score-exp is a single ex2
                v0 = (v0 + bq[col]) * (0.125f * LOG2E);
                v1 = (v1 + bq[col + 1]) * (0.125f * LOG2E);
                int hd = col >> 6, dd = col & 63;
                *(__half2*)(g_Q + ((b * NH + hd) * LSEQ + l) * DDIM + dd) =
                    __floats2half2_rn(v0, v1);
            } else {
                int cj = col - 512;
                v0 += bk[cj];
                v1 += bk[cj + 1];
                int hd = cj >> 6, dd = cj & 63;
                *(__half2*)(g_K + ((b * NH + hd) * LSEQ + l) * DDIM + dd) =
                    __floats2half2_rn(v0, v1);
            }
        }
    }
}

// ---------------- kernel 3: V (sigmoid(x @ Wv), flipped) ----------------
__global__ void __launch_bounds__(256) v_kernel(const float* __restrict__ x,
                                                const float* __restrict__ Wv) {
    __shared__ float Wsh[256 * 8];
    __shared__ float Xsh[32 * 257];
    int tid = threadIdx.x;
    for (int i = tid; i < 2048; i += 256) Wsh[i] = Wv[i];
    int row0 = blockIdx.x * 32;
    for (int i = tid; i < 8192; i += 256) {
        int r = i >> 8, c = i & 255;
        Xsh[r * 257 + c] = x[(row0 + r) * 256 + c];
    }
    __syncthreads();
    int r = tid >> 3, h = tid & 7;
    int bl = row0 + r;
    float s = 0.f;
#pragma unroll 8
    for (int kk = 0; kk < 256; kk++) s += Xsh[r * 257 + kk] * Wsh[kk * 8 + h];
    float v = 1.f / (1.f + __expf(-s));
    int b = bl >> 11, l = bl & (LSEQ - 1);
    g_V[(b * NH + h) * LSEQ + (LSEQ - 1 - l)] = v;
}

// ---------------- kernel 4: attention (4x2 grid, f16 acc, f16x2 exp) ----------------
__global__ void __launch_bounds__(256, 6) attn_kernel() {
    __shared__ __half Kb[3][64 * LDP];      // Kb[2] doubles as Q staging at start
    __shared__ float dsh[64];
    __shared__ float Ssh[DBINS];
    __shared__ float Vsh[5 * 64];

    int tid = threadIdx.x, lane = tid & 31, w = tid >> 5, wy = w >> 1, wx = w & 1;
    int qt = blockIdx.x, bh = blockIdx.y;
    int q0 = qt << 6;
    const __half* Qg = g_Q + (bh * LSEQ + q0) * DDIM;
    const __half* Kg = g_K + bh * LSEQ * DDIM;

    // async-load Q (into Kb[2]) + first two K tiles
    cp_tile(Kb[2], Qg, tid);
    cp_tile(Kb[0], Kg, tid);
    cp_commit();                    // group: Q + K0
    cp_tile(Kb[1], Kg + 64 * DDIM, tid);
    cp_commit();                    // group: K1

    if (tid < 64) dsh[tid] = 0.f;
    if (tid < DBINS) Ssh[tid] = 0.f;
    if (tid == 255) Ssh[256] = 0.f;

    cp_wait1();                     // Q + K0 landed
    __syncthreads();

    // hoist A (Q) fragments for this warp's 16 rows: Af[kc][4] = 16 regs
    uint32_t Af[4][4];
    {
        uint32_t a_addr = sptr(Kb[2] + (wy * 16 + (lane & 15)) * LDP + ((lane >> 4) << 3));
#pragma unroll
        for (int kc = 0; kc < 4; kc++)
            ldsm4(Af[kc][0], Af[kc][1], Af[kc][2], Af[kc][3], a_addr + kc * 32);
    }
    __syncthreads();                // all warps done reading Q before Kb[2] is reused

    int g = lane >> 2, tc = lane & 3;
    float dsum0 = 0.f, dsum1 = 0.f;

    // ---- Phase 1: softmax denominators over all 32 K tiles ----
    for (int kt = 0; kt < 32; kt++) {
        if (kt > 0) { cp_wait1(); __syncthreads(); }
        if (kt + 2 < 32) cp_tile(Kb[(kt + 2) % 3], Kg + (kt + 2) * 64 * DDIM, tid);
        cp_commit();                // one group per iteration -> constant wait_group 1
        uint32_t acc[4][2];
#pragma unroll
        for (int i = 0; i < 4; i++) { acc[i][0] = 0u; acc[i][1] = 0u; }
        mma_h(Kb[kt % 3], Af, acc, lane, wx);
        // packed exp + half2 tree-sum, then fold into fp32 once per tile
        uint32_t h0 = h2add(h2add(h2ex2(acc[0][0]), h2ex2(acc[1][0])),
                            h2add(h2ex2(acc[2][0]), h2ex2(acc[3][0])));
        uint32_t h1 = h2add(h2add(h2ex2(acc[0][1]), h2ex2(acc[1][1])),
                            h2add(h2ex2(acc[2][1]), h2ex2(acc[3][1])));
        float2 f0 = __half22float2(*(__half2*)&h0);
        float2 f1 = __half22float2(*(__half2*)&h1);
        dsum0 += f0.x + f0.y;
        dsum1 += f1.x + f1.y;
    }
    // reduce over the 4 tc-lanes sharing a row, then shared atomics across warps
    dsum0 += __shfl_xor_sync(0xffffffffu, dsum0, 1);
    dsum0 += __shfl_xor_sync(0xffffffffu, dsum0, 2);
    dsum1 += __shfl_xor_sync(0xffffffffu, dsum1, 1);
    dsum1 += __shfl_xor_sync(0xffffffffu, dsum1, 2);
    if (tc == 0) {
        atomicAdd(&dsh[wy * 16 + g], dsum0);
        atomicAdd(&dsh[wy * 16 + g + 8], dsum1);
    }
    __syncthreads();

    int kt_lo = qt >= 2 ? qt - 2 : 0;
    int kt_hi = qt <= 29 ? qt + 2 : 31;
    int nb = kt_hi - kt_lo + 1;

    if (tid < 64) dsh[tid] = 1.f / dsh[tid];
    const float* Vg = g_V + bh * LSEQ;
    for (int i = tid; i < nb * 64; i += 256) Vsh[i] = Vg[kt_lo * 64 + i];
    __syncthreads();   // buffers free + dsh inverted

    float inv0 = dsh[wy * 16 + g];
    float inv1 = dsh[wy * 16 + g + 8];

    // ---- Phase 2: band tiles, bin by diagonal j = 128 + k - q ----
    cp_tile(Kb[0], Kg + kt_lo * 64 * DDIM, tid);
    cp_commit();
    if (nb > 1) cp_tile(Kb[1], Kg + (kt_lo + 1) * 64 * DDIM, tid);
    cp_commit();

    for (int i = 0; i < nb; i++) {
        int kt = kt_lo + i;
        cp_wait1();
        __syncthreads();
        if (i + 2 < nb) cp_tile(Kb[(i + 2) % 3], Kg + (kt + 2) * 64 * DDIM, tid);
        cp_commit();
        uint32_t acc[4][2];
#pragma unroll
        for (int ii = 0; ii < 4; ii++) { acc[ii][0] = 0u; acc[ii][1] = 0u; }
        mma_h(Kb[i % 3], Af, acc, lane, wx);
#pragma unroll
        for (int nt = 0; nt < 4; nt++) {
            int kb = (kt << 6) + wx * 32 + nt * 8 + tc * 2;
#pragma unroll
            for (int hh = 0; hh < 2; hh++) {
                int q = q0 + wy * 16 + g + (hh << 3);
                float iv = hh ? inv1 : inv0;
                uint32_t eh = h2ex2(acc[nt][hh]);
                float2 e = __half22float2(*(__half2*)&eh);
                int j0 = MDIST + kb - q;
                if (j0 >= 0 && j0 < DBINS)
                    atomicAdd(&Ssh[j0], e.x * iv * Vsh[kb - (kt_lo << 6)]);
                int j1 = j0 + 1;
                if (j1 >= 0 && j1 < DBINS)
                    atomicAdd(&Ssh[j1], e.y * iv * Vsh[kb + 1 - (kt_lo << 6)]);
            }
        }
    }
    __syncthreads();
    if (tid < DBINS) atomicAdd(&g_S[bh * DBINS + tid], Ssh[tid]);
    if (tid == 255) atomicAdd(&g_S[bh * DBINS + 256], Ssh[256]);
}

// ---------------- kernel 5: window smoothing + output ----------------
__global__ void final_kernel(float* __restrict__ out) {
    int idx = blockIdx.x * 256 + threadIdx.x;
    if (idx >= NB * DBINS * NH) return;
    int h = idx & 7;
    int j = (idx >> 3) % DBINS;
    int b = idx / (DBINS * NH);
    const float* S = g_S + (b * NH + h) * DBINS;
    float s = S[j];
    float cnt = 1.f;
    if (j > 0)         { s += S[j - 1]; cnt += 1.f; }
    if (j < DBINS - 1) { s += S[j + 1]; cnt += 1.f; }
    out[idx] = s / cnt;
}

// ---------------- launch ----------------
extern "C" void kernel_launch(void* const* d_in, const int* in_sizes, int n_in,
                              void* d_out, int out_size) {
    const float* x  = (const float*)d_in[0];
    const float* pe = (const float*)d_in[1];
    const float* Wq = (const float*)d_in[2];
    const float* bq = (const float*)d_in[3];
    const float* Wk = (const float*)d_in[4];
    const float* bk = (const float*)d_in[5];
    const float* Wv = (const float*)d_in[6];
    float* out = (float*)d_out;

    int prep_total = 8192 * 256 + 1024 * 256 + NBH * DBINS;
    prep_kernel<<<(prep_total + 255) / 256, 256>>>(x, pe, Wq, Wk);
    proj_kernel<<<dim3(128, 16), 256>>>(bq, bk);
    v_kernel<<<256, 256>>>(x, Wv);
    attn_kernel<<<dim3(32, 32), 256>>>();
    final_kernel<<<(NB * DBINS * NH + 255) / 256, 256>>>(out);
}

// round 6
// speedup vs baseline: 1.2182x; 1.0959x over previous
#include <cuda_runtime.h>
#include <cuda_fp16.h>
#include <cstdint>

#define LSEQ 2048
#define NH   8
#define DDIM 64
#define NB   4
#define NBH  32          // NB*NH
#define MDIST 128
#define DBINS 257
#define LDP  72          // padded shared row stride (halves): 144B -> conflict-free ldmatrix
#define LOG2E 1.4426950408889634f

// ---------------- scratch (device globals; no runtime alloc) ----------------
__device__ __half g_qkin[8192 * 256];       // x+pe, fp16
__device__ __half g_Wt[1024 * 256];         // [Wq|Wk]^T, n-major rows, k contiguous
__device__ __half g_Q[NBH * LSEQ * DDIM];   // scaled by d^-0.5 * log2(e), +bias
__device__ __half g_K[NBH * LSEQ * DDIM];
__device__ float  g_V[NBH * LSEQ];          // Vflip[b,h,k] = sigmoid(x[b,L-1-k] . Wv[:,h])
__device__ float  g_S[NBH * DBINS];         // diagonal-bin accumulator

// ---------------- helpers ----------------
__device__ __forceinline__ uint32_t sptr(const void* p) {
    return (uint32_t)__cvta_generic_to_shared(p);
}

__device__ __forceinline__ uint32_t h2ex2(uint32_t x) {   // packed half2 2^x
    uint32_t r;
    asm("ex2.approx.f16x2 %0, %1;\n" : "=r"(r) : "r"(x));
    return r;
}

__device__ __forceinline__ uint32_t h2add(uint32_t a, uint32_t b) {
    uint32_t r;
    asm("add.f16x2 %0, %1, %2;\n" : "=r"(r) : "r"(a), "r"(b));
    return r;
}

__device__ __forceinline__ void ldsm4(uint32_t& r0, uint32_t& r1, uint32_t& r2, uint32_t& r3,
                                      uint32_t addr) {
    asm volatile("ldmatrix.sync.aligned.m8n8.x4.shared.b16 {%0,%1,%2,%3}, [%4];\n"
                 : "=r"(r0), "=r"(r1), "=r"(r2), "=r"(r3) : "r"(addr));
}

// fp32-accumulate variant (proj kernel)
__device__ __forceinline__ void mma16816(float* c, uint32_t a0, uint32_t a1, uint32_t a2,
                                         uint32_t a3, uint32_t b0, uint32_t b1) {
    asm volatile(
        "mma.sync.aligned.m16n8k16.row.col.f32.f16.f16.f32 "
        "{%0,%1,%2,%3},{%4,%5,%6,%7},{%8,%9},{%0,%1,%2,%3};\n"
        : "+f"(c[0]), "+f"(c[1]), "+f"(c[2]), "+f"(c[3])
        : "r"(a0), "r"(a1), "r"(a2), "r"(a3), "r"(b0), "r"(b1));
}

// f16-accumulate variant (attention): C/D = 2 packed-half2 regs
__device__ __forceinline__ void mma16816h(uint32_t& c0, uint32_t& c1, uint32_t a0, uint32_t a1,
                                          uint32_t a2, uint32_t a3, uint32_t b0, uint32_t b1) {
    asm volatile(
        "mma.sync.aligned.m16n8k16.row.col.f16.f16.f16.f16 "
        "{%0,%1},{%2,%3,%4,%5},{%6,%7},{%0,%1};\n"
        : "+r"(c0), "+r"(c1)
        : "r"(a0), "r"(a1), "r"(a2), "r"(a3), "r"(b0), "r"(b1));
}

__device__ __forceinline__ void cp_async16(uint32_t dst, const void* src) {
    asm volatile("cp.async.ca.shared.global [%0], [%1], 16;\n" :: "r"(dst), "l"(src));
}
__device__ __forceinline__ void cp_commit() { asm volatile("cp.async.commit_group;\n"); }
__device__ __forceinline__ void cp_wait1()  { asm volatile("cp.async.wait_group 1;\n"); }
__device__ __forceinline__ void cp_wait0()  { asm volatile("cp.async.wait_group 0;\n"); }

// async copy of a 64x64 half tile (global row stride = 64) into padded shared tile
__device__ __forceinline__ void cp_tile(__half* dst, const __half* src, int tid) {
    int r = tid >> 3, c = (tid & 7) << 3;
    cp_async16(sptr(dst + r * LDP + c), src + r * 64 + c);
    cp_async16(sptr(dst + (r + 32) * LDP + c), src + (r + 32) * 64 + c);
}

// Dual-subtile MMA: B fragments loaded once, applied to both Q subtiles.
// acc[sub][nt][hh]; Af[sub][kc][4].
__device__ __forceinline__ void mma_h2(const __half* Ks, const uint32_t Af[2][4][4],
                                       uint32_t acc[2][4][2], int lane, int wx) {
    int brow = wx * 32 + (lane & 7) + ((lane >> 4) << 3);
    int bcol = ((lane >> 3) & 1) << 3;
    uint32_t b_addr0 = sptr(Ks + brow * LDP + bcol);
    uint32_t b_addr1 = b_addr0 + 16 * LDP * 2;
#pragma unroll
    for (int kc = 0; kc < 4; kc++) {
        uint32_t b0, b1, b2, b3, b4, b5, b6, b7;
        ldsm4(b0, b1, b2, b3, b_addr0 + kc * 32);
        ldsm4(b4, b5, b6, b7, b_addr1 + kc * 32);
#pragma unroll
        for (int sub = 0; sub < 2; sub++) {
            mma16816h(acc[sub][0][0], acc[sub][0][1], Af[sub][kc][0], Af[sub][kc][1],
                      Af[sub][kc][2], Af[sub][kc][3], b0, b1);
            mma16816h(acc[sub][1][0], acc[sub][1][1], Af[sub][kc][0], Af[sub][kc][1],
                      Af[sub][kc][2], Af[sub][kc][3], b2, b3);
            mma16816h(acc[sub][2][0], acc[sub][2][1], Af[sub][kc][0], Af[sub][kc][1],
                      Af[sub][kc][2], Af[sub][kc][3], b4, b5);
            mma16816h(acc[sub][3][0], acc[sub][3][1], Af[sub][kc][0], Af[sub][kc][1],
                      Af[sub][kc][2], Af[sub][kc][3], b6, b7);
        }
    }
}

// sync-copy 64x64 halves (global stride STRIDE) into padded shared tile (for proj kernel)
#define LOAD_TILE(DST, SRC, STRIDE)                                                   \
    {                                                                                 \
        int r_ = tid >> 3, c_ = (tid & 7) << 3;                                       \
        *(int4*)((DST) + r_ * LDP + c_) = *(const int4*)((SRC) + r_ * (STRIDE) + c_); \
        *(int4*)((DST) + (r_ + 32) * LDP + c_) =                                      \
            *(const int4*)((SRC) + (r_ + 32) * (STRIDE) + c_);                        \
    }

// full 64x64 mma loading both A and B from shared (proj kernel, 4x2 warp grid)
__device__ __forceinline__ void mma_tile_64(const __half* Qs, const __half* Ks,
                                            float acc[16], int lane, int wy, int wx) {
    uint32_t a_addr = sptr(Qs + (wy * 16 + (lane & 15)) * LDP + ((lane >> 4) << 3));
    int brow = wx * 32 + (lane & 7) + ((lane >> 4) << 3);
    int bcol = ((lane >> 3) & 1) << 3;
    uint32_t b_addr0 = sptr(Ks + brow * LDP + bcol);
    uint32_t b_addr1 = b_addr0 + 16 * LDP * 2;
#pragma unroll
    for (int kc = 0; kc < 4; kc++) {
        uint32_t a0, a1, a2, a3, b0, b1, b2, b3, b4, b5, b6, b7;
        ldsm4(a0, a1, a2, a3, a_addr + kc * 32);
        ldsm4(b0, b1, b2, b3, b_addr0 + kc * 32);
        ldsm4(b4, b5, b6, b7, b_addr1 + kc * 32);
        mma16816(acc + 0,  a0, a1, a2, a3, b0, b1);
        mma16816(acc + 4,  a0, a1, a2, a3, b2, b3);
        mma16816(acc + 8,  a0, a1, a2, a3, b4, b5);
        mma16816(acc + 12, a0, a1, a2, a3, b6, b7);
    }
}

// ---------------- kernel 1: prep ----------------
__global__ void prep_kernel(const float* __restrict__ x, const float* __restrict__ pe,
                            const float* __restrict__ Wq, const float* __restrict__ Wk) {
    int idx = blockIdx.x * 256 + threadIdx.x;
    if (idx < 8192 * 256) {
        int row = idx >> 8;
        int l = row & (LSEQ - 1);
        int c = idx & 255;
        g_qkin[idx] = __float2half(x[idx] + pe[l * 256 + c]);
        return;
    }
    int i2 = idx - 8192 * 256;
    if (i2 < 1024 * 256) {
        int n = i2 >> 8, kk = i2 & 255;
        float w = (n < 512) ? Wq[kk * 512 + n] : Wk[kk * 512 + (n - 512)];
        g_Wt[i2] = __float2half(w);
        return;
    }
    int i3 = i2 - 1024 * 256;
    if (i3 < NBH * DBINS) g_S[i3] = 0.f;
}

// ---------------- kernel 2: Q/K projection GEMM ----------------
__global__ void __launch_bounds__(256) proj_kernel(const float* __restrict__ bq,
                                                   const float* __restrict__ bk) {
    __shared__ __half As[64 * LDP];
    __shared__ __half Bs[64 * LDP];
    int tid = threadIdx.x, lane = tid & 31, w = tid >> 5, wy = w >> 1, wx = w & 1;
    int m0 = blockIdx.x << 6, n0 = blockIdx.y << 6;
    float acc[16];
#pragma unroll
    for (int i = 0; i < 16; i++) acc[i] = 0.f;
    for (int ks = 0; ks < 4; ks++) {
        __syncthreads();
        LOAD_TILE(As, g_qkin + m0 * 256 + (ks << 6), 256);
        LOAD_TILE(Bs, g_Wt + n0 * 256 + (ks << 6), 256);
        __syncthreads();
        mma_tile_64(As, Bs, acc, lane, wy, wx);
    }
    int g = lane >> 2, tc = lane & 3;
#pragma unroll
    for (int nt = 0; nt < 4; nt++) {
#pragma unroll
        for (int hh = 0; hh < 2; hh++) {
            int row = m0 + wy * 16 + g + (hh << 3);
            int col = n0 + wx * 32 + nt * 8 + tc * 2;
            float v0 = acc[nt * 4 + hh * 2 + 0];
            float v1 = acc[nt * 4 + hh * 2 + 1];
            int b = row >> 11, l = row & (LSEQ - 1);
            if (col < 512) {
                // fold d^-0.5 and log2(e) into Q so score-exp is a single ex2
                v0 = (v0 + bq[col]) * (0.125f * LOG2E);
                v1 = (v1 + bq[col + 1]) * (0.125f * LOG2E);
                int hd = col >> 6, dd = col & 63;
                *(__half2*)(g_Q + ((b * NH + hd) * LSEQ + l) * DDIM + dd) =
                    __floats2half2_rn(v0, v1);
            } else {
                int cj = col - 512;
                v0 += bk[cj];
                v1 += bk[cj + 1];
                int hd = cj >> 6, dd = cj & 63;
                *(__half2*)(g_K + ((b * NH + hd) * LSEQ + l) * DDIM + dd) =
                    __floats2half2_rn(v0, v1);
            }
        }
    }
}

// ---------------- kernel 3: V (sigmoid(x @ Wv), flipped) ----------------
__global__ void __launch_bounds__(256) v_kernel(const float* __restrict__ x,
                                                const float* __restrict__ Wv) {
    __shared__ float Wsh[256 * 8];
    __shared__ float Xsh[32 * 257];
    int tid = threadIdx.x;
    for (int i = tid; i < 2048; i += 256) Wsh[i] = Wv[i];
    int row0 = blockIdx.x * 32;
    for (int i = tid; i < 8192; i += 256) {
        int r = i >> 8, c = i & 255;
        Xsh[r * 257 + c] = x[(row0 + r) * 256 + c];
    }
    __syncthreads();
    int r = tid >> 3, h = tid & 7;
    int bl = row0 + r;
    float s = 0.f;
#pragma unroll 8
    for (int kk = 0; kk < 256; kk++) s += Xsh[r * 257 + kk] * Wsh[kk * 8 + h];
    float v = 1.f / (1.f + __expf(-s));
    int b = bl >> 11, l = bl & (LSEQ - 1);
    g_V[(b * NH + h) * LSEQ + (LSEQ - 1 - l)] = v;
}

// ---------------- kernel 4: attention (128-row Q block per CTA) ----------------
__global__ void __launch_bounds__(256, 4) attn_kernel() {
    __shared__ __half Kb[3][64 * LDP];      // K ring; Kb[0],Kb[1] stage Q at start
    __shared__ float dsh[128];
    __shared__ float Ssh[DBINS];
    __shared__ float Vsh[6 * 64];

    int tid = threadIdx.x, lane = tid & 31, w = tid >> 5, wy = w >> 1, wx = w & 1;
    int qb = blockIdx.x, bh = blockIdx.y;   // qb: 128-row Q block (0..15)
    int q0 = qb << 7;
    const __half* Qg = g_Q + (bh * LSEQ + q0) * DDIM;
    const __half* Kg = g_K + bh * LSEQ * DDIM;

    // stage both Q subtiles, extract fragments
    cp_tile(Kb[0], Qg, tid);
    cp_tile(Kb[1], Qg + 64 * DDIM, tid);
    cp_commit();

    if (tid < 128) dsh[tid] = 0.f;
    if (tid < DBINS) Ssh[tid] = 0.f;
    if (tid == 255) Ssh[256] = 0.f;

    cp_wait0();
    __syncthreads();

    uint32_t Af[2][4][4];                   // [sub][kc][frag] = 32 regs
#pragma unroll
    for (int sub = 0; sub < 2; sub++) {
        uint32_t a_addr =
            sptr(Kb[sub] + (wy * 16 + (lane & 15)) * LDP + ((lane >> 4) << 3));
#pragma unroll
        for (int kc = 0; kc < 4; kc++)
            ldsm4(Af[sub][kc][0], Af[sub][kc][1], Af[sub][kc][2], Af[sub][kc][3],
                  a_addr + kc * 32);
    }
    __syncthreads();                        // done reading Q; Kb reusable

    int g = lane >> 2, tc = lane & 3;
    float dsum[2][2];                       // [sub][hh]
    dsum[0][0] = dsum[0][1] = dsum[1][0] = dsum[1][1] = 0.f;

    // ---- Phase 1: softmax denominators over all 32 K tiles ----
    cp_tile(Kb[0], Kg, tid);
    cp_commit();
    cp_tile(Kb[1], Kg + 64 * DDIM, tid);
    cp_commit();
    for (int kt = 0; kt < 32; kt++) {
        cp_wait1();
        __syncthreads();
        {   // always commit a real group (clamped) so wait_group 1 stays sound
            int pf = kt + 2 < 32 ? kt + 2 : 31;
            cp_tile(Kb[(kt + 2) % 3], Kg + pf * 64 * DDIM, tid);
            cp_commit();
        }
        uint32_t acc[2][4][2];
#pragma unroll
        for (int s = 0; s < 2; s++)
#pragma unroll
            for (int n = 0; n < 4; n++) { acc[s][n][0] = 0u; acc[s][n][1] = 0u; }
        mma_h2(Kb[kt % 3], Af, acc, lane, wx);
#pragma unroll
        for (int sub = 0; sub < 2; sub++) {
            uint32_t h0 = h2add(h2add(h2ex2(acc[sub][0][0]), h2ex2(acc[sub][1][0])),
                                h2add(h2ex2(acc[sub][2][0]), h2ex2(acc[sub][3][0])));
            uint32_t h1 = h2add(h2add(h2ex2(acc[sub][0][1]), h2ex2(acc[sub][1][1])),
                                h2add(h2ex2(acc[sub][2][1]), h2ex2(acc[sub][3][1])));
            float2 f0 = __half22float2(*(__half2*)&h0);
            float2 f1 = __half22float2(*(__half2*)&h1);
            dsum[sub][0] += f0.x + f0.y;
            dsum[sub][1] += f1.x + f1.y;
        }
    }
    // reduce over the 4 tc-lanes sharing a row, then shared atomics across warps
#pragma unroll
    for (int sub = 0; sub < 2; sub++)
#pragma unroll
        for (int hh = 0; hh < 2; hh++) {
            dsum[sub][hh] += __shfl_xor_sync(0xffffffffu, dsum[sub][hh], 1);
            dsum[sub][hh] += __shfl_xor_sync(0xffffffffu, dsum[sub][hh], 2);
        }
    if (tc == 0) {
#pragma unroll
        for (int sub = 0; sub < 2; sub++) {
            atomicAdd(&dsh[sub * 64 + wy * 16 + g], dsum[sub][0]);
            atomicAdd(&dsh[sub * 64 + wy * 16 + g + 8], dsum[sub][1]);
        }
    }
    __syncthreads();

    // band k-tiles for q in [q0, q0+127]: k in [q0-128, q0+255]
    int kt_lo = qb >= 1 ? 2 * qb - 2 : 0;
    int kt_hi = qb <= 14 ? 2 * qb + 3 : 31;
    int nb = kt_hi - kt_lo + 1;             // 4..6

    if (tid < 128) dsh[tid] = 1.f / dsh[tid];
    const float* Vg = g_V + bh * LSEQ;
    for (int i = tid; i < nb * 64; i += 256) Vsh[i] = Vg[kt_lo * 64 + i];
    __syncthreads();                        // buffers free + dsh inverted

    float inv[2][2];
#pragma unroll
    for (int sub = 0; sub < 2; sub++) {
        inv[sub][0] = dsh[sub * 64 + wy * 16 + g];
        inv[sub][1] = dsh[sub * 64 + wy * 16 + g + 8];
    }

    // ---- Phase 2: band tiles, bin by diagonal j = 128 + k - q ----
    cp_tile(Kb[0], Kg + kt_lo * 64 * DDIM, tid);
    cp_commit();
    cp_tile(Kb[1], Kg + (kt_lo + 1) * 64 * DDIM, tid);
    cp_commit();
    for (int i = 0; i < nb; i++) {
        int kt = kt_lo + i;
        cp_wait1();
        __syncthreads();
        {
            int pf = i + 2 < nb ? kt + 2 : kt_hi;
            cp_tile(Kb[(i + 2) % 3], Kg + pf * 64 * DDIM, tid);
            cp_commit();
        }
        uint32_t acc[2][4][2];
#pragma unroll
        for (int s = 0; s < 2; s++)
#pragma unroll
            for (int n = 0; n < 4; n++) { acc[s][n][0] = 0u; acc[s][n][1] = 0u; }
        mma_h2(Kb[i % 3], Af, acc, lane, wx);
#pragma unroll
        for (int sub = 0; sub < 2; sub++) {
#pragma unroll
            for (int nt = 0; nt < 4; nt++) {
                int kb = (kt << 6) + wx * 32 + nt * 8 + tc * 2;
                int vix = kb - (kt_lo << 6);
#pragma unroll
                for (int hh = 0; hh < 2; hh++) {
                    int q = q0 + sub * 64 + wy * 16 + g + (hh << 3);
                    float iv = inv[sub][hh];
                    uint32_t eh = h2ex2(acc[sub][nt][hh]);
                    float2 e = __half22float2(*(__half2*)&eh);
                    int j0 = MDIST + kb - q;
                    if (j0 >= 0 && j0 < DBINS)
                        atomicAdd(&Ssh[j0], e.x * iv * Vsh[vix]);
                    int j1 = j0 + 1;
                    if (j1 >= 0 && j1 < DBINS)
                        atomicAdd(&Ssh[j1], e.y * iv * Vsh[vix + 1]);
                }
            }
        }
    }
    __syncthreads();
    if (tid < DBINS) atomicAdd(&g_S[bh * DBINS + tid], Ssh[tid]);
    if (tid == 255) atomicAdd(&g_S[bh * DBINS + 256], Ssh[256]);
}

// ---------------- kernel 5: window smoothing + output ----------------
__global__ void final_kernel(float* __restrict__ out) {
    int idx = blockIdx.x * 256 + threadIdx.x;
    if (idx >= NB * DBINS * NH) return;
    int h = idx & 7;
    int j = (idx >> 3) % DBINS;
    int b = idx / (DBINS * NH);
    const float* S = g_S + (b * NH + h) * DBINS;
    float s = S[j];
    float cnt = 1.f;
    if (j > 0)         { s += S[j - 1]; cnt += 1.f; }
    if (j < DBINS - 1) { s += S[j + 1]; cnt += 1.f; }
    out[idx] = s / cnt;
}

// ---------------- launch ----------------
extern "C" void kernel_launch(void* const* d_in, const int* in_sizes, int n_in,
                              void* d_out, int out_size) {
    const float* x  = (const float*)d_in[0];
    const float* pe = (const float*)d_in[1];
    const float* Wq = (const float*)d_in[2];
    const float* bq = (const float*)d_in[3];
    const float* Wk = (const float*)d_in[4];
    const float* bk = (const float*)d_in[5];
    const float* Wv = (const float*)d_in[6];
    float* out = (float*)d_out;

    int prep_total = 8192 * 256 + 1024 * 256 + NBH * DBINS;
    prep_kernel<<<(prep_total + 255) / 256, 256>>>(x, pe, Wq, Wk);
    proj_kernel<<<dim3(128, 16), 256>>>(bq, bk);
    v_kernel<<<256, 256>>>(x, Wv);
    attn_kernel<<<dim3(16, 32), 256>>>();
    final_kernel<<<(NB * DBINS * NH + 255) / 256, 256>>>(out);
}